// round 15
// baseline (speedup 1.0000x reference)
#include <cuda_runtime.h>
#include <cstdint>

#define HASH_SIZE (1u << 19)
#define HASH_MASK (HASH_SIZE - 1u)
#define PRIME_X 73856093u
#define PRIME_Y 19349663u
#define ROWS_PER_BLOCK 128     // 128 rows x 128B = 16KB smem
#define THREADS 128            // 16 groups of 8; UNROLL 8 rows per thread-slot
#define UNROLL 8

// One-shot blocks, cp.async gathers (no result regs), smem staging, one bulk
// store. Key resource = outstanding gather bytes/SM = blocks x tile_bytes,
// smem-capped at ~224KB. R13 (256thr) was thread-limited to 8x16KB=128KB;
// 128-thr blocks let ~13 blocks co-reside -> ~210KB in flight.
__global__ void __launch_bounds__(THREADS)
hashgrid_gather_kernel(const float2* __restrict__ positions,
                       const float4* __restrict__ table,
                       float4* __restrict__ out,
                       int n) {
    __shared__ __align__(128) float4 buf[ROWS_PER_BLOCK * 8];  // 16 KB

    int tid  = threadIdx.x;
    int part = tid & 7;           // which float4 of the 128B row
    int lgrp = tid >> 3;          // local row group 0..15
    int base = blockIdx.x * ROWS_PER_BLOCK;

    uint32_t smem_base = (uint32_t)__cvta_generic_to_shared(buf);

    int      r[UNROLL];
    float2   p[UNROLL];
    uint32_t h[UNROLL];

    // Phase 1: batch position loads (independent -> front-batched LDGs)
    #pragma unroll
    for (int u = 0; u < UNROLL; u++) {
        r[u] = base + lgrp + u * 16;
        if (r[u] < n) p[u] = __ldg(&positions[r[u]]);
    }

    // Phase 2: hashes. Low 19 bits of the int64 products depend only on the
    // low 32 bits -> uint32 math reproduces the reference exactly; floorf is
    // exact for uniform [0, 4096) positions.
    #pragma unroll
    for (int u = 0; u < UNROLL; u++) {
        uint32_t ix = (uint32_t)(int)floorf(p[u].x);
        uint32_t iy = (uint32_t)(int)floorf(p[u].y);
        h[u] = ((ix * PRIME_X) ^ (iy * PRIME_Y)) & HASH_MASK;
    }

    // Phase 3: 8 independent 16B cp.async gathers per thread (no result regs)
    #pragma unroll
    for (int u = 0; u < UNROLL; u++) {
        if (r[u] < n) {
            const float4* src = &table[(size_t)h[u] * 8 + part];
            uint32_t dst = smem_base + (uint32_t)(((lgrp + u * 16) * 8 + part) * 16);
            asm volatile("cp.async.cg.shared.global [%0], [%1], 16;"
                         :: "r"(dst), "l"(src));
        }
    }
    asm volatile("cp.async.commit_group;");
    asm volatile("cp.async.wait_group 0;");
    asm volatile("fence.proxy.async.shared::cta;" ::: "memory");
    __syncthreads();

    // Phase 4: single bulk async store of the contiguous tile. Wait only for
    // the smem READ side — the global-write tail overlaps the next block.
    if (tid == 0) {
        int rows = n - base;
        rows = rows < ROWS_PER_BLOCK ? rows : ROWS_PER_BLOCK;
        if (rows > 0) {
            uint32_t bytes = (uint32_t)rows * 128u;
            asm volatile("cp.async.bulk.global.shared::cta.bulk_group [%0], [%1], %2;"
                         :: "l"(out + (size_t)base * 8), "r"(smem_base), "r"(bytes)
                         : "memory");
            asm volatile("cp.async.bulk.commit_group;");
            asm volatile("cp.async.bulk.wait_group.read 0;" ::: "memory");
        }
    }
}

extern "C" void kernel_launch(void* const* d_in, const int* in_sizes, int n_in,
                              void* d_out, int out_size) {
    const float2* positions = (const float2*)d_in[0];   // [N, 2] float32
    const float4* table     = (const float4*)d_in[1];   // [HASH_SIZE, 32] float32
    float4* out             = (float4*)d_out;           // [N, 32] float32

    int n = in_sizes[0] / 2;    // N positions
    int grid = (n + ROWS_PER_BLOCK - 1) / ROWS_PER_BLOCK;

    hashgrid_gather_kernel<<<grid, THREADS>>>(positions, table, out, n);
}

// round 17
// speedup vs baseline: 1.0801x; 1.0801x over previous
#include <cuda_runtime.h>
#include <cstdint>

#define HASH_SIZE (1u << 19)
#define HASH_MASK (HASH_SIZE - 1u)
#define PRIME_X 73856093u
#define PRIME_Y 19349663u
#define ROWS_PER_BLOCK 128     // 128 rows x 128B = 16KB smem -> 8 blocks/SM
#define THREADS 256
#define UNROLL 4               // 32 groups of 8 threads; 4 rows per slot

// R13 structure (best so far) + L2 residency policies:
//  - gathers: cp.async with evict_last policy -> pin the 64MB table in L2
//  - output:  bulk store with evict_first policy -> the 256MB write-once
//    stream stops evicting table lines
// Goal: steady-state table fully L2-resident (64MB < 126MB, L2 persists
// across graph replays) -> DRAM becomes a near-pure sequential write stream.
__global__ void __launch_bounds__(THREADS)
hashgrid_gather_kernel(const float2* __restrict__ positions,
                       const float4* __restrict__ table,
                       float4* __restrict__ out,
                       int n) {
    __shared__ __align__(128) float4 buf[ROWS_PER_BLOCK * 8];  // 16 KB

    int tid  = threadIdx.x;
    int part = tid & 7;           // which float4 of the 128B row
    int lgrp = tid >> 3;          // local row group 0..31
    int base = blockIdx.x * ROWS_PER_BLOCK;

    uint32_t smem_base = (uint32_t)__cvta_generic_to_shared(buf);

    uint64_t pol_keep, pol_stream;
    asm volatile("createpolicy.fractional.L2::evict_last.b64 %0, 1.0;"
                 : "=l"(pol_keep));
    asm volatile("createpolicy.fractional.L2::evict_first.b64 %0, 1.0;"
                 : "=l"(pol_stream));

    int      r[UNROLL];
    float2   p[UNROLL];
    uint32_t h[UNROLL];

    // Phase 1: batch position loads (independent -> front-batched LDGs)
    #pragma unroll
    for (int u = 0; u < UNROLL; u++) {
        r[u] = base + lgrp + u * 32;
        if (r[u] < n) p[u] = __ldg(&positions[r[u]]);
    }

    // Phase 2: hashes. Low 19 bits of the int64 products depend only on the
    // low 32 bits -> uint32 math reproduces the reference exactly; floorf is
    // exact for uniform [0, 4096) positions.
    #pragma unroll
    for (int u = 0; u < UNROLL; u++) {
        uint32_t ix = (uint32_t)(int)floorf(p[u].x);
        uint32_t iy = (uint32_t)(int)floorf(p[u].y);
        h[u] = ((ix * PRIME_X) ^ (iy * PRIME_Y)) & HASH_MASK;
    }

    // Phase 3: 4 independent 16B cp.async gathers per thread, evict_last
    // policy keeps the table resident against the output stream.
    #pragma unroll
    for (int u = 0; u < UNROLL; u++) {
        if (r[u] < n) {
            const float4* src = &table[(size_t)h[u] * 8 + part];
            uint32_t dst = smem_base + (uint32_t)(((lgrp + u * 32) * 8 + part) * 16);
            asm volatile("cp.async.cg.shared.global.L2::cache_hint [%0], [%1], 16, %2;"
                         :: "r"(dst), "l"(src), "l"(pol_keep));
        }
    }
    asm volatile("cp.async.commit_group;");
    asm volatile("cp.async.wait_group 0;");
    asm volatile("fence.proxy.async.shared::cta;" ::: "memory");
    __syncthreads();

    // Phase 4: bulk async store with evict_first (write-once output must not
    // displace table lines). Wait only for the smem READ side.
    if (tid == 0) {
        int rows = n - base;
        rows = rows < ROWS_PER_BLOCK ? rows : ROWS_PER_BLOCK;
        if (rows > 0) {
            uint32_t bytes = (uint32_t)rows * 128u;
            asm volatile(
                "cp.async.bulk.global.shared::cta.bulk_group.L2::cache_hint"
                " [%0], [%1], %2, %3;"
                :: "l"(out + (size_t)base * 8), "r"(smem_base), "r"(bytes),
                   "l"(pol_stream)
                : "memory");
            asm volatile("cp.async.bulk.commit_group;");
            asm volatile("cp.async.bulk.wait_group.read 0;" ::: "memory");
        }
    }
}

extern "C" void kernel_launch(void* const* d_in, const int* in_sizes, int n_in,
                              void* d_out, int out_size) {
    const float2* positions = (const float2*)d_in[0];   // [N, 2] float32
    const float4* table     = (const float4*)d_in[1];   // [HASH_SIZE, 32] float32
    float4* out             = (float4*)d_out;           // [N, 32] float32

    int n = in_sizes[0] / 2;    // N positions
    int grid = (n + ROWS_PER_BLOCK - 1) / ROWS_PER_BLOCK;

    hashgrid_gather_kernel<<<grid, THREADS>>>(positions, table, out, n);
}